// round 5
// baseline (speedup 1.0000x reference)
#include <cuda_runtime.h>
#include <math.h>

#define B_ 8
#define N_ 8192
#define D_ 256

// ---------------- device scratch (static, no allocation) ----------------
__device__ float g_WvT[D_ * D_];
__device__ float g_G[B_ * D_ * D_];
__device__ float g_T[B_ * D_ * D_];
__device__ float g_S[B_ * D_ * D_];
__device__ float g_C[B_ * D_ * D_];
__device__ float g_sk[B_ * D_];
__device__ float g_sv[B_ * D_];
__device__ float g_u[B_ * D_];
__device__ float g_w[B_ * D_];
__device__ float g_r[B_ * D_];
__device__ float g_cnt[B_];
__device__ float g_biasflag;
__device__ unsigned char g_mask8[B_ * N_];   // canonical mask: 1 = padded
__device__ int g_notint, g_notfloat;

// ---------------- f32x2 helpers ----------------
__device__ __forceinline__ unsigned long long pack2(float x, float y) {
    unsigned long long r;
    asm("mov.b64 %0, {%1, %2};" : "=l"(r) : "f"(x), "f"(y));
    return r;
}
__device__ __forceinline__ void unpack2(unsigned long long v, float &x, float &y) {
    asm("mov.b64 {%0, %1}, %2;" : "=f"(x), "=f"(y) : "l"(v));
}
__device__ __forceinline__ void ffma2(unsigned long long &d, unsigned long long a,
                                      unsigned long long b) {
    asm("fma.rn.f32x2 %0, %1, %2, %0;" : "+l"(d) : "l"(a), "l"(b));
}

// ---------------- mask dtype detection + canonicalization ----------------
__global__ void k_maskflags() { g_notint = 0; g_notfloat = 0; }

// Sample first 16384 int32 / float32 words (= 65536 bytes, safe under every
// possible mask dtype since the smallest candidate buffer is B*N uint8 bytes).
__global__ void k_maskdetect(const void* mp) {
    int i = blockIdx.x * blockDim.x + threadIdx.x;   // [0, 16384)
    int v = ((const int*)mp)[i];
    if (v != 0 && v != 1) atomicOr(&g_notint, 1);
    float f = ((const float*)mp)[i];
    if (!(f == 0.0f || f == 1.0f)) atomicOr(&g_notfloat, 1);
}

__global__ void k_maskconv(const void* mp) {
    int i = blockIdx.x * blockDim.x + threadIdx.x;   // [0, B*N)
    unsigned char m;
    if (!g_notint)        m = (((const int*)mp)[i] != 0);
    else if (!g_notfloat) m = (((const float*)mp)[i] != 0.0f);
    else                  m = (((const unsigned char*)mp)[i] != 0);
    g_mask8[i] = m;
}

// ---------------- generic tiled GEMM ----------------
// C[m][n] (+)= sum_k A(k,m) * B(k,n) over this CTA's k-chunk
//   AKM  = true : A K-major (A[k][m] at A[k*ldA+m]); false: A m-major
//   MASKA: zero A rows where g_mask8[k]
//   EPI: 0=store 1=atomicAdd 2=scale*(acc+bias-rank1) 3=acc+r[col]
template <int BM, int BN, int TM, int TN, int KSTEP, bool AKM, bool MASKA, int EPI>
__global__ void __launch_bounds__((BM / TM) * (BN / TN)) gemm_tpl(
    const float* __restrict__ Ag, const float* __restrict__ Bg, float* __restrict__ Cg,
    int K, int nchunks,
    long sAb, long sBb, long sCb,
    int ldA, int ldB, int ldC,
    const float* __restrict__ bkv, const float* __restrict__ bvv,
    float scale)
{
    constexpr int TX = BN / TN;
    constexpr int TY = BM / TM;
    constexpr int NT = TX * TY;

    const int t  = threadIdx.x;
    const int tx = t % TX;
    const int ty = t / TX;

    const int b    = blockIdx.z / nchunks;
    const int ch   = blockIdx.z % nchunks;
    const int kLen = K / nchunks;
    const int kbeg = ch * kLen;

    const float* A  = Ag + (long)b * sAb;
    const float* Bm = Bg + (long)b * sBb;
    float*       C  = Cg + (long)b * sCb;
    const unsigned char* mp = MASKA ? (g_mask8 + (long)b * N_) : nullptr;

    const int m0 = blockIdx.y * BM;
    const int n0 = blockIdx.x * BN;

    __shared__ float sA[AKM ? (KSTEP * BM) : (BM * (KSTEP + 1))];
    __shared__ float sB[KSTEP * BN];

    unsigned long long acc[TM][TN / 2];
#pragma unroll
    for (int i = 0; i < TM; i++)
#pragma unroll
        for (int j = 0; j < TN / 2; j++) acc[i][j] = 0ull;

    for (int k0 = kbeg; k0 < kbeg + kLen; k0 += KSTEP) {
        if constexpr (AKM) {
            constexpr int AF4 = KSTEP * BM / 4;
#pragma unroll
            for (int r = 0; r < AF4 / NT; r++) {
                int i  = t + r * NT;
                int kk = i / (BM / 4);
                int mq = i % (BM / 4);
                float4 v = *(const float4*)(A + (long)(k0 + kk) * ldA + m0 + mq * 4);
                if constexpr (MASKA) {
                    float ml = mp[k0 + kk] ? 0.0f : 1.0f;
                    v.x *= ml; v.y *= ml; v.z *= ml; v.w *= ml;
                }
                *(float4*)(&sA[kk * BM + mq * 4]) = v;
            }
        } else {
            constexpr int AF4 = BM * (KSTEP / 4);
#pragma unroll
            for (int r = 0; r < AF4 / NT; r++) {
                int i  = t + r * NT;
                int mr = i / (KSTEP / 4);
                int kq = i % (KSTEP / 4);
                float4 v = *(const float4*)(A + (long)(m0 + mr) * ldA + k0 + kq * 4);
                int base = mr * (KSTEP + 1) + kq * 4;
                sA[base + 0] = v.x; sA[base + 1] = v.y;
                sA[base + 2] = v.z; sA[base + 3] = v.w;
            }
        }
        {
            constexpr int BF4 = KSTEP * BN / 4;
#pragma unroll
            for (int r = 0; r < BF4 / NT; r++) {
                int i  = t + r * NT;
                int kk = i / (BN / 4);
                int nq = i % (BN / 4);
                float4 v = *(const float4*)(Bm + (long)(k0 + kk) * ldB + n0 + nq * 4);
                *(float4*)(&sB[kk * BN + nq * 4]) = v;
            }
        }
        __syncthreads();

#pragma unroll 4
        for (int kk = 0; kk < KSTEP; kk++) {
            unsigned long long bb[TN / 2];
            const unsigned long long* bp =
                reinterpret_cast<const unsigned long long*>(&sB[kk * BN + tx * TN]);
#pragma unroll
            for (int j = 0; j < TN / 2; j++) bb[j] = bp[j];

            float av[TM];
            if constexpr (AKM) {
#pragma unroll
                for (int q = 0; q < TM / 4; q++) {
                    float4 va = *(const float4*)(&sA[kk * BM + ty * TM + q * 4]);
                    av[q * 4 + 0] = va.x; av[q * 4 + 1] = va.y;
                    av[q * 4 + 2] = va.z; av[q * 4 + 3] = va.w;
                }
            } else {
#pragma unroll
                for (int i = 0; i < TM; i++)
                    av[i] = sA[(ty * TM + i) * (KSTEP + 1) + kk];
            }
#pragma unroll
            for (int i = 0; i < TM; i++) {
                unsigned long long aa = pack2(av[i], av[i]);
#pragma unroll
                for (int j = 0; j < TN / 2; j++) ffma2(acc[i][j], aa, bb[j]);
            }
        }
        __syncthreads();
    }

#pragma unroll
    for (int i = 0; i < TM; i++) {
        int m = m0 + ty * TM + i;
        float vals[TN];
#pragma unroll
        for (int j = 0; j < TN / 2; j++) unpack2(acc[i][j], vals[2 * j], vals[2 * j + 1]);
        float* crow = C + (long)m * ldC + n0 + tx * TN;

        if constexpr (EPI == 1) {
#pragma unroll
            for (int j = 0; j < TN; j++) atomicAdd(&crow[j], vals[j]);
        } else if constexpr (EPI == 2) {
            float um  = g_u[b * D_ + m];
            float bkm = bkv[m];
            float cb  = g_cnt[b];
#pragma unroll
            for (int j = 0; j < TN; j++) {
                int col = n0 + tx * TN + j;
                crow[j] = scale * (vals[j] + um * bvv[col] + bkm * g_w[b * D_ + col]
                                   + cb * bkm * bvv[col]);
            }
        } else if constexpr (EPI == 3) {
#pragma unroll
            for (int q = 0; q < TN / 4; q++) {
                int col = n0 + tx * TN + q * 4;
                float4 o;
                o.x = vals[q * 4 + 0] + g_r[b * D_ + col + 0];
                o.y = vals[q * 4 + 1] + g_r[b * D_ + col + 1];
                o.z = vals[q * 4 + 2] + g_r[b * D_ + col + 2];
                o.w = vals[q * 4 + 3] + g_r[b * D_ + col + 3];
                *(float4*)(&crow[q * 4]) = o;
            }
        } else {
#pragma unroll
            for (int q = 0; q < TN / 4; q++) {
                float4 o;
                o.x = vals[q * 4 + 0]; o.y = vals[q * 4 + 1];
                o.z = vals[q * 4 + 2]; o.w = vals[q * 4 + 3];
                *(float4*)(&crow[q * 4]) = o;
            }
        }
    }
}

// ---------------- small kernels ----------------
__global__ void k_zero() {
    int i = blockIdx.x * blockDim.x + threadIdx.x;
    if (i < B_ * D_ * D_) g_G[i] = 0.0f;
    if (i < B_ * D_) { g_sk[i] = 0.0f; g_sv[i] = 0.0f; }
    if (i < B_) g_cnt[i] = 0.0f;
}

__global__ void k_flag(const float* __restrict__ bk, const float* __restrict__ bv) {
    __shared__ float red[D_];
    int t = threadIdx.x;
    red[t] = fabsf(bk[t]) + fabsf(bv[t]);
    __syncthreads();
    for (int s = 128; s > 0; s >>= 1) {
        if (t < s) red[t] += red[t + s];
        __syncthreads();
    }
    if (t == 0) g_biasflag = red[0];
}

__global__ void k_tr(const float* __restrict__ Wv) {
    g_WvT[blockIdx.x * D_ + threadIdx.x] = Wv[threadIdx.x * D_ + blockIdx.x];
}

__global__ void k_sums(const float* __restrict__ key, const float* __restrict__ val) {
    if (g_biasflag == 0.0f) return;
    int b = blockIdx.x;
    int d = threadIdx.x;
    float sk = 0.0f, sv = 0.0f, c = 0.0f;
    for (int n = 0; n < N_; n++) {
        float ml = g_mask8[(long)b * N_ + n] ? 0.0f : 1.0f;
        sk += ml * key[((long)b * N_ + n) * D_ + d];
        sv += ml * val[((long)b * N_ + n) * D_ + d];
        c  += ml;
    }
    g_sk[b * D_ + d] = sk;
    g_sv[b * D_ + d] = sv;
    if (d == 0) g_cnt[b] = c;
}

__global__ void k_uw(const float* __restrict__ Wk, const float* __restrict__ Wv) {
    int b = blockIdx.x;
    int d = threadIdx.x;
    float u = 0.0f, w = 0.0f;
    for (int j = 0; j < D_; j++) {
        u += Wk[d * D_ + j] * g_sk[b * D_ + j];
        w += g_sv[b * D_ + j] * Wv[d * D_ + j];
    }
    g_u[b * D_ + d] = u;
    g_w[b * D_ + d] = w;
}

__global__ void k_softmax() {
    int b = blockIdx.x;
    int e = threadIdx.x;
    float* p = g_S + (long)b * D_ * D_ + e;
    float mx = -1e30f;
    for (int d = 0; d < D_; d++) mx = fmaxf(mx, p[d * D_]);
    float s = 0.0f;
    for (int d = 0; d < D_; d++) {
        float v = expf(p[d * D_] - mx);
        s += v;
        p[d * D_] = v;
    }
    float inv = 1.0f / s;
    for (int d = 0; d < D_; d++) p[d * D_] *= inv;
}

__global__ void k_r(const float* __restrict__ bq) {
    int b = blockIdx.x;
    int e = threadIdx.x;
    float r = 0.0f;
    for (int d = 0; d < D_; d++) r += bq[d] * g_S[(long)b * D_ * D_ + d * D_ + e];
    g_r[b * D_ + e] = r;
}

// ---------------- launch ----------------
extern "C" void kernel_launch(void* const* d_in, const int* in_sizes, int n_in,
                              void* d_out, int out_size)
{
    const float* query = (const float*)d_in[0];
    const float* key   = (const float*)d_in[1];
    const float* value = (const float*)d_in[2];
    const void*  maskp = d_in[3];

    int wbase = 4;
    if (wbase < n_in && in_sizes[wbase] < 32) wbase++;   // skip need_weights scalar

    const float* Wq = (const float*)d_in[wbase + 0];
    const float* bq = (const float*)d_in[wbase + 1];
    const float* Wk = (const float*)d_in[wbase + 2];
    const float* bk = (const float*)d_in[wbase + 3];
    const float* Wv = (const float*)d_in[wbase + 4];
    const float* bv = (const float*)d_in[wbase + 5];
    float* out = (float*)d_out;

    float *pG, *pT, *pS, *pC, *pWvT;
    cudaGetSymbolAddress((void**)&pG, g_G);
    cudaGetSymbolAddress((void**)&pT, g_T);
    cudaGetSymbolAddress((void**)&pS, g_S);
    cudaGetSymbolAddress((void**)&pC, g_C);
    cudaGetSymbolAddress((void**)&pWvT, g_WvT);

    const float scale = 0.3535533905932738f;  // 1/sqrt(B)

    // 0. mask canonicalization (dtype-agnostic)
    k_maskflags<<<1, 1>>>();
    k_maskdetect<<<16384 / 256, 256>>>(maskp);
    k_maskconv<<<(B_ * N_) / 256, 256>>>(maskp);

    // 1. zero accumulators, bias flag, Wv transpose
    k_zero<<<(B_ * D_ * D_ + 255) / 256, 256>>>();
    k_flag<<<1, D_>>>(bk, bv);
    k_tr<<<D_, D_>>>(Wv);

    // 2. G[b] = sum_n mask * key_n value_n^T  (K=8192, split 16-way, atomic accum)
    gemm_tpl<128, 128, 8, 8, 32, true, true, 1>
        <<<dim3(2, 2, B_ * 16), 256>>>(key, value, pG,
                                       N_, 16,
                                       (long)N_ * D_, (long)N_ * D_, (long)D_ * D_,
                                       D_, D_, D_, nullptr, nullptr, 0.0f);

    // 3. bias-path sums (early-exit when biases are zero)
    k_sums<<<B_, D_>>>(key, value);
    k_uw<<<B_, D_>>>(Wk, Wv);

    // 4. T = Wk @ G
    gemm_tpl<64, 64, 4, 4, 32, false, false, 0>
        <<<dim3(4, 4, B_), 256>>>(Wk, pG, pT,
                                  D_, 1,
                                  0L, (long)D_ * D_, (long)D_ * D_,
                                  D_, D_, D_, nullptr, nullptr, 0.0f);

    // 5. S = scale * (T @ WvT + bias terms)
    gemm_tpl<64, 64, 4, 4, 32, false, false, 2>
        <<<dim3(4, 4, B_), 256>>>(pT, pWvT, pS,
                                  D_, 1,
                                  (long)D_ * D_, 0L, (long)D_ * D_,
                                  D_, D_, D_, bk, bv, scale);

    // 6. softmax over d, then r = bq @ aw
    k_softmax<<<B_, D_>>>();
    k_r<<<B_, D_>>>(bq);

    // 7. C = Wq^T @ aw
    gemm_tpl<64, 64, 4, 4, 32, true, false, 0>
        <<<dim3(4, 4, B_), 256>>>(Wq, pS, pC,
                                  D_, 1,
                                  0L, (long)D_ * D_, (long)D_ * D_,
                                  D_, D_, D_, nullptr, nullptr, 0.0f);

    // 8. out = query @ C + r
    gemm_tpl<128, 128, 8, 8, 32, false, false, 3>
        <<<dim3(2, 64, B_), 256>>>(query, pC, out,
                                   D_, 1,
                                   (long)N_ * D_, (long)D_ * D_, (long)N_ * D_,
                                   D_, D_, D_, nullptr, nullptr, 0.0f);
}